// round 4
// baseline (speedup 1.0000x reference)
#include <cuda_runtime.h>
#include <cuda_bf16.h>
#include <cstdint>

// SE3 Hamiltonian NODE dynamics: per-row map over [BS, 22] f32.
// Persistent double-buffered TMA pipeline: cp.async.bulk gmem<->smem,
// one row per thread, conflict-free float2 smem access.

#define TILE_ROWS  250
#define TPB        256
#define ROW_F      22
#define ROW_F2     11
#define TILE_F     (TILE_ROWS * ROW_F)   // 5500 floats
#define TILE_BYTES (TILE_F * 4)          // 22000 B (16B multiple)
#define NBUF       2
#define MAX_CTAS   760                   // ~5 CTAs/SM * 152 SMs

// Constants folded at compile time from the same double expressions the
// reference uses (rounded to f32, matching jnp.float32 casts).
#define M1c    ((float)(1.0 / (1.0 / 0.027)))
#define M1INVc ((float)(1.0 / 0.027))
#define J0c    ((float)(2.3951e-05))
#define J2c    ((float)(3.2347e-05))
#define JI0c   ((float)(1.0 / 2.3951e-05))
#define JI2c   ((float)(1.0 / 3.2347e-05))
#define MGc    ((float)(0.027 * 9.81))

__device__ __forceinline__ void se3_row_compute(const float* __restrict__ v,
                                                float* __restrict__ o) {
    const float R00 = v[3],  R01 = v[4],  R02 = v[5];
    const float R10 = v[6],  R11 = v[7],  R12 = v[8];
    const float R20 = v[9],  R21 = v[10], R22 = v[11];

    const float pv0 = v[12] * M1c, pv1 = v[13] * M1c, pv2 = v[14] * M1c;
    const float pw0 = v[15] * J0c, pw1 = v[16] * J0c, pw2 = v[17] * J2c;

    const float gv0 = pv0 * M1INVc, gv1 = pv1 * M1INVc, gv2 = pv2 * M1INVc;
    const float gw0 = pw0 * JI0c,   gw1 = pw1 * JI0c,   gw2 = pw2 * JI2c;

    o[0] = R00 * gv0 + R01 * gv1 + R02 * gv2;
    o[1] = R10 * gv0 + R11 * gv1 + R12 * gv2;
    o[2] = R20 * gv0 + R21 * gv1 + R22 * gv2;

    o[3]  = R01 * gw2 - R02 * gw1;
    o[4]  = R02 * gw0 - R00 * gw2;
    o[5]  = R00 * gw1 - R01 * gw0;
    o[6]  = R11 * gw2 - R12 * gw1;
    o[7]  = R12 * gw0 - R10 * gw2;
    o[8]  = R10 * gw1 - R11 * gw0;
    o[9]  = R21 * gw2 - R22 * gw1;
    o[10] = R22 * gw0 - R20 * gw2;
    o[11] = R20 * gw1 - R21 * gw0;

    const float dpv0 = (pv1 * gw2 - pv2 * gw1) - MGc * R20;
    const float dpv1 = (pv2 * gw0 - pv0 * gw2) - MGc * R21;
    const float dpv2 = (pv0 * gw1 - pv1 * gw0) - MGc * R22 + v[18];

    const float dpw0 = (pw1 * gw2 - pw2 * gw1) + (pv1 * gv2 - pv2 * gv1) + v[19];
    const float dpw1 = (pw2 * gw0 - pw0 * gw2) + (pv2 * gv0 - pv0 * gv2) + v[20];
    const float dpw2 = (pw0 * gw1 - pw1 * gw0) + (pv0 * gv1 - pv1 * gv0) + v[21];

    o[12] = dpv0 * M1INVc;
    o[13] = dpv1 * M1INVc;
    o[14] = dpv2 * M1INVc;
    o[15] = dpw0 * JI0c;
    o[16] = dpw1 * JI0c;
    o[17] = dpw2 * JI2c;

    o[18] = 0.0f; o[19] = 0.0f; o[20] = 0.0f; o[21] = 0.0f;
}

__device__ __forceinline__ uint32_t smem_u32(const void* p) {
    uint32_t a;
    asm("{ .reg .u64 t; cvta.to.shared.u64 t, %1; cvt.u32.u64 %0, t; }"
        : "=r"(a) : "l"(p));
    return a;
}

__device__ __forceinline__ void mbar_init(uint32_t m) {
    asm volatile("mbarrier.init.shared::cta.b64 [%0], 1;" :: "r"(m) : "memory");
}
__device__ __forceinline__ void tma_load_tile(uint32_t sdst, const float* gsrc,
                                              uint32_t m) {
    asm volatile("mbarrier.arrive.expect_tx.shared::cta.b64 _, [%0], %1;"
                 :: "r"(m), "r"((uint32_t)TILE_BYTES) : "memory");
    asm volatile("cp.async.bulk.shared::cta.global.mbarrier::complete_tx::bytes "
                 "[%0], [%1], %2, [%3];"
                 :: "r"(sdst), "l"(gsrc), "r"((uint32_t)TILE_BYTES), "r"(m)
                 : "memory");
}
__device__ __forceinline__ void mbar_wait(uint32_t m, uint32_t parity) {
    uint32_t done = 0;
    while (!done) {
        asm volatile(
            "{ .reg .pred p; "
            "mbarrier.try_wait.parity.shared::cta.b64 p, [%1], %2; "
            "selp.b32 %0, 1, 0, p; }"
            : "=r"(done) : "r"(m), "r"(parity) : "memory");
    }
}

__global__ __launch_bounds__(TPB)
void SE3HamNODEGT_kernel(const float* __restrict__ in, float* __restrict__ out,
                         int nrows, int ntiles) {
    __shared__ alignas(16) float s[NBUF][TILE_F];
    __shared__ alignas(8) unsigned long long mbar[NBUF];

    const int tid = threadIdx.x;
    const uint32_t m0 = smem_u32(&mbar[0]);
    const uint32_t m1 = smem_u32(&mbar[1]);
    const uint32_t s0 = smem_u32(&s[0][0]);
    const uint32_t s1 = smem_u32(&s[1][0]);

    if (tid == 0) {
        mbar_init(m0);
        mbar_init(m1);
        asm volatile("fence.proxy.async.shared::cta;" ::: "memory");
    }
    __syncthreads();

    const long long t0 = blockIdx.x;
    const long long gstride = gridDim.x;

    // Prologue: fill the pipeline with up to NBUF loads.
    if (tid == 0) {
        if (t0 < ntiles)           tma_load_tile(s0, in + t0 * TILE_F, m0);
        if (t0 + gstride < ntiles) tma_load_tile(s1, in + (t0 + gstride) * TILE_F, m1);
    }

    uint32_t ph0 = 0, ph1 = 0;
    long long k = 0;
    for (long long t = t0; t < ntiles; t += gstride, ++k) {
        const int b = (int)(k & 1);
        const uint32_t mb = b ? m1 : m0;
        const uint32_t sb = b ? s1 : s0;
        float* sp = s[b];

        // Wait for this tile's TMA load (visibility via complete_tx).
        mbar_wait(mb, b ? ph1 : ph0);
        if (b) ph1 ^= 1; else ph0 ^= 1;

        if (tid < TILE_ROWS) {
            float v[ROW_F], o[ROW_F];
            const float2* r2 = reinterpret_cast<const float2*>(sp) + tid * ROW_F2;
            #pragma unroll
            for (int j = 0; j < ROW_F2; j++) {
                float2 x = r2[j];
                v[2 * j] = x.x;
                v[2 * j + 1] = x.y;
            }
            se3_row_compute(v, o);
            float2* w2 = reinterpret_cast<float2*>(sp) + tid * ROW_F2;
            #pragma unroll
            for (int j = 0; j < ROW_F2; j++)
                w2[j] = make_float2(o[2 * j], o[2 * j + 1]);
        }
        __syncthreads();

        if (tid == 0) {
            // Publish generic smem writes to the async proxy, then bulk store.
            asm volatile("fence.proxy.async.shared::cta;" ::: "memory");
            asm volatile("cp.async.bulk.global.shared::cta.bulk_group [%0], [%1], %2;"
                         :: "l"(out + t * TILE_F), "r"(sb),
                            "r"((uint32_t)TILE_BYTES) : "memory");
            asm volatile("cp.async.bulk.commit_group;" ::: "memory");
            // Wait until the store has *read* smem (fast), then refill this
            // buffer with the load for tile t + 2*gstride.
            asm volatile("cp.async.bulk.wait_group.read 0;" ::: "memory");
            const long long tn = t + 2 * gstride;
            if (tn < ntiles)
                tma_load_tile(sb, in + tn * TILE_F, mb);
        }
    }

    // Generic tail (no tail for BS=2e6: 2e6 = 250 * 8000): block 0, direct gmem.
    const long long tail_start = (long long)ntiles * TILE_ROWS;
    if (blockIdx.x == 0 && tail_start < nrows) {
        for (long long r = tail_start + tid; r < nrows; r += TPB) {
            float v[ROW_F], o[ROW_F];
            #pragma unroll
            for (int j = 0; j < ROW_F; j++) v[j] = in[r * ROW_F + j];
            se3_row_compute(v, o);
            #pragma unroll
            for (int j = 0; j < ROW_F; j++) out[r * ROW_F + j] = o[j];
        }
    }
}

extern "C" void kernel_launch(void* const* d_in, const int* in_sizes, int n_in,
                              void* d_out, int out_size) {
    const float* in = nullptr;
    for (int i = 0; i < n_in; i++) {
        if (in_sizes[i] == out_size) { in = (const float*)d_in[i]; break; }
    }
    if (!in) {
        int best = 0;
        for (int i = 1; i < n_in; i++) if (in_sizes[i] > in_sizes[best]) best = i;
        in = (const float*)d_in[best];
    }

    const int nrows = out_size / ROW_F;
    const int ntiles = nrows / TILE_ROWS;
    int blocks = ntiles < MAX_CTAS ? (ntiles > 0 ? ntiles : 1) : MAX_CTAS;
    SE3HamNODEGT_kernel<<<blocks, TPB>>>(in, (float*)d_out, nrows, ntiles);
}

// round 5
// speedup vs baseline: 1.0890x; 1.0890x over previous
#include <cuda_runtime.h>
#include <cuda_bf16.h>
#include <cstdint>

// SE3 Hamiltonian NODE dynamics: per-row map over [BS, 22] f32.
// TMA-streaming kernel, one 128-row tile per CTA (oversubscribed grid is the
// pipeline): cp.async.bulk gmem->smem->gmem, one row per thread,
// conflict-free float2 smem access.

#define TILE_ROWS  128
#define TPB        128
#define ROW_F      22
#define ROW_F2     11
#define TILE_F     (TILE_ROWS * ROW_F)   // 2816 floats
#define TILE_BYTES (TILE_F * 4)          // 11264 B (16B multiple)

// Constants folded at compile time from the same double expressions the
// reference uses (rounded to f32, matching jnp.float32 casts).
#define M1c    ((float)(1.0 / (1.0 / 0.027)))
#define M1INVc ((float)(1.0 / 0.027))
#define J0c    ((float)(2.3951e-05))
#define J2c    ((float)(3.2347e-05))
#define JI0c   ((float)(1.0 / 2.3951e-05))
#define JI2c   ((float)(1.0 / 3.2347e-05))
#define MGc    ((float)(0.027 * 9.81))

__device__ __forceinline__ void se3_row_compute(const float* __restrict__ v,
                                                float* __restrict__ o) {
    const float R00 = v[3],  R01 = v[4],  R02 = v[5];
    const float R10 = v[6],  R11 = v[7],  R12 = v[8];
    const float R20 = v[9],  R21 = v[10], R22 = v[11];

    const float pv0 = v[12] * M1c, pv1 = v[13] * M1c, pv2 = v[14] * M1c;
    const float pw0 = v[15] * J0c, pw1 = v[16] * J0c, pw2 = v[17] * J2c;

    const float gv0 = pv0 * M1INVc, gv1 = pv1 * M1INVc, gv2 = pv2 * M1INVc;
    const float gw0 = pw0 * JI0c,   gw1 = pw1 * JI0c,   gw2 = pw2 * JI2c;

    o[0] = R00 * gv0 + R01 * gv1 + R02 * gv2;
    o[1] = R10 * gv0 + R11 * gv1 + R12 * gv2;
    o[2] = R20 * gv0 + R21 * gv1 + R22 * gv2;

    o[3]  = R01 * gw2 - R02 * gw1;
    o[4]  = R02 * gw0 - R00 * gw2;
    o[5]  = R00 * gw1 - R01 * gw0;
    o[6]  = R11 * gw2 - R12 * gw1;
    o[7]  = R12 * gw0 - R10 * gw2;
    o[8]  = R10 * gw1 - R11 * gw0;
    o[9]  = R21 * gw2 - R22 * gw1;
    o[10] = R22 * gw0 - R20 * gw2;
    o[11] = R20 * gw1 - R21 * gw0;

    const float dpv0 = (pv1 * gw2 - pv2 * gw1) - MGc * R20;
    const float dpv1 = (pv2 * gw0 - pv0 * gw2) - MGc * R21;
    const float dpv2 = (pv0 * gw1 - pv1 * gw0) - MGc * R22 + v[18];

    const float dpw0 = (pw1 * gw2 - pw2 * gw1) + (pv1 * gv2 - pv2 * gv1) + v[19];
    const float dpw1 = (pw2 * gw0 - pw0 * gw2) + (pv2 * gv0 - pv0 * gv2) + v[20];
    const float dpw2 = (pw0 * gw1 - pw1 * gw0) + (pv0 * gv1 - pv1 * gv0) + v[21];

    o[12] = dpv0 * M1INVc;
    o[13] = dpv1 * M1INVc;
    o[14] = dpv2 * M1INVc;
    o[15] = dpw0 * JI0c;
    o[16] = dpw1 * JI0c;
    o[17] = dpw2 * JI2c;

    o[18] = 0.0f; o[19] = 0.0f; o[20] = 0.0f; o[21] = 0.0f;
}

__device__ __forceinline__ uint32_t smem_u32(const void* p) {
    uint32_t a;
    asm("{ .reg .u64 t; cvta.to.shared.u64 t, %1; cvt.u32.u64 %0, t; }"
        : "=r"(a) : "l"(p));
    return a;
}

__global__ __launch_bounds__(TPB)
void SE3HamNODEGT_kernel(const float* __restrict__ in, float* __restrict__ out,
                         int nrows) {
    __shared__ alignas(16) float s[TILE_F];
    __shared__ alignas(8) unsigned long long mbar;

    const int tid = threadIdx.x;
    const long long base_row  = (long long)blockIdx.x * TILE_ROWS;
    const long long base_elem = base_row * ROW_F;

    const uint32_t s_addr = smem_u32(s);
    const uint32_t m_addr = smem_u32(&mbar);

    const bool full = (base_row + TILE_ROWS) <= (long long)nrows;

    if (full) {
        // Issue TMA load immediately from tid 0.
        if (tid == 0) {
            asm volatile("mbarrier.init.shared::cta.b64 [%0], 1;" :: "r"(m_addr) : "memory");
            asm volatile("fence.proxy.async.shared::cta;" ::: "memory");
            asm volatile("mbarrier.arrive.expect_tx.shared::cta.b64 _, [%0], %1;"
                         :: "r"(m_addr), "r"((uint32_t)TILE_BYTES) : "memory");
            asm volatile("cp.async.bulk.shared::cta.global.mbarrier::complete_tx::bytes "
                         "[%0], [%1], %2, [%3];"
                         :: "r"(s_addr), "l"(in + base_elem),
                            "r"((uint32_t)TILE_BYTES), "r"(m_addr) : "memory");
        }
        __syncthreads();

        // Wait for TMA load (phase 0), HW-sleep wait with timeout hint.
        {
            uint32_t done;
            asm volatile(
                "{ .reg .pred p; "
                "mbarrier.try_wait.parity.shared::cta.b64 p, [%1], 0, 10000000; "
                "selp.b32 %0, 1, 0, p; }"
                : "=r"(done) : "r"(m_addr) : "memory");
            while (!done) {
                asm volatile(
                    "{ .reg .pred p; "
                    "mbarrier.try_wait.parity.shared::cta.b64 p, [%1], 0, 10000000; "
                    "selp.b32 %0, 1, 0, p; }"
                    : "=r"(done) : "r"(m_addr) : "memory");
            }
        }

        // One row per thread; conflict-free float2 access (row start 8B
        // aligned; word stride 22 -> LDS.64 16-lane phases hit distinct banks).
        float v[ROW_F], o[ROW_F];
        {
            const float2* r2 = reinterpret_cast<const float2*>(s) + tid * ROW_F2;
            #pragma unroll
            for (int k = 0; k < ROW_F2; k++) {
                float2 x = r2[k];
                v[2 * k]     = x.x;
                v[2 * k + 1] = x.y;
            }
        }

        se3_row_compute(v, o);

        {
            float2* w2 = reinterpret_cast<float2*>(s) + tid * ROW_F2;
            #pragma unroll
            for (int k = 0; k < ROW_F2; k++)
                w2[k] = make_float2(o[2 * k], o[2 * k + 1]);
        }

        // Publish generic smem writes to the async proxy, then bulk store.
        asm volatile("fence.proxy.async.shared::cta;" ::: "memory");
        __syncthreads();

        if (tid == 0) {
            asm volatile("cp.async.bulk.global.shared::cta.bulk_group [%0], [%1], %2;"
                         :: "l"(out + base_elem), "r"(s_addr),
                            "r"((uint32_t)TILE_BYTES) : "memory");
            asm volatile("cp.async.bulk.commit_group;" ::: "memory");
            asm volatile("cp.async.bulk.wait_group.read 0;" ::: "memory");
        }
        // tid 0 keeps the CTA alive until the TMA store has read smem.
    } else {
        // Tail block (not hit for BS=2e6): guarded scalar path.
        const long long total = (long long)nrows * ROW_F;
        for (int i = tid; i < TILE_F; i += TPB) {
            long long g = base_elem + i;
            if (g < total) s[i] = in[g];
        }
        __syncthreads();

        const long long row = base_row + tid;
        float v[ROW_F], o[ROW_F];
        if (row < nrows) {
            #pragma unroll
            for (int j = 0; j < ROW_F; j++) v[j] = s[tid * ROW_F + j];
            se3_row_compute(v, o);
            #pragma unroll
            for (int j = 0; j < ROW_F; j++) s[tid * ROW_F + j] = o[j];
        }
        __syncthreads();

        for (int i = tid; i < TILE_F; i += TPB) {
            long long g = base_elem + i;
            if (g < total) out[g] = s[i];
        }
    }
}

extern "C" void kernel_launch(void* const* d_in, const int* in_sizes, int n_in,
                              void* d_out, int out_size) {
    const float* in = nullptr;
    for (int i = 0; i < n_in; i++) {
        if (in_sizes[i] == out_size) { in = (const float*)d_in[i]; break; }
    }
    if (!in) {
        int best = 0;
        for (int i = 1; i < n_in; i++) if (in_sizes[i] > in_sizes[best]) best = i;
        in = (const float*)d_in[best];
    }

    const int nrows = out_size / ROW_F;
    const int blocks = (nrows + TILE_ROWS - 1) / TILE_ROWS;
    SE3HamNODEGT_kernel<<<blocks, TPB>>>(in, (float*)d_out, nrows);
}

// round 6
// speedup vs baseline: 1.1040x; 1.0138x over previous
#include <cuda_runtime.h>
#include <cuda_bf16.h>
#include <cstdint>

// SE3 Hamiltonian NODE dynamics: per-row map over [BS, 22] f32.
// Warp-independent TMA pipelines: each warp owns a 32-row chunk with its own
// mbarrier + cp.async.bulk load/store. No block barriers in the hot path.

#define TILE_ROWS  128
#define TPB        128
#define NWARP      4
#define WARP_ROWS  32
#define ROW_F      22
#define ROW_F2     11
#define TILE_F     (TILE_ROWS * ROW_F)    // 2816 floats
#define WARP_F     (WARP_ROWS * ROW_F)    // 704 floats
#define WARP_BYTES (WARP_F * 4)           // 2816 B (16B multiple)

// Constants folded at compile time from the same double expressions the
// reference uses (rounded to f32, matching jnp.float32 casts).
#define M1c    ((float)(1.0 / (1.0 / 0.027)))
#define M1INVc ((float)(1.0 / 0.027))
#define J0c    ((float)(2.3951e-05))
#define J2c    ((float)(3.2347e-05))
#define JI0c   ((float)(1.0 / 2.3951e-05))
#define JI2c   ((float)(1.0 / 3.2347e-05))
#define MGc    ((float)(0.027 * 9.81))

__device__ __forceinline__ void se3_row_compute(const float* __restrict__ v,
                                                float* __restrict__ o) {
    const float R00 = v[3],  R01 = v[4],  R02 = v[5];
    const float R10 = v[6],  R11 = v[7],  R12 = v[8];
    const float R20 = v[9],  R21 = v[10], R22 = v[11];

    const float pv0 = v[12] * M1c, pv1 = v[13] * M1c, pv2 = v[14] * M1c;
    const float pw0 = v[15] * J0c, pw1 = v[16] * J0c, pw2 = v[17] * J2c;

    const float gv0 = pv0 * M1INVc, gv1 = pv1 * M1INVc, gv2 = pv2 * M1INVc;
    const float gw0 = pw0 * JI0c,   gw1 = pw1 * JI0c,   gw2 = pw2 * JI2c;

    o[0] = R00 * gv0 + R01 * gv1 + R02 * gv2;
    o[1] = R10 * gv0 + R11 * gv1 + R12 * gv2;
    o[2] = R20 * gv0 + R21 * gv1 + R22 * gv2;

    o[3]  = R01 * gw2 - R02 * gw1;
    o[4]  = R02 * gw0 - R00 * gw2;
    o[5]  = R00 * gw1 - R01 * gw0;
    o[6]  = R11 * gw2 - R12 * gw1;
    o[7]  = R12 * gw0 - R10 * gw2;
    o[8]  = R10 * gw1 - R11 * gw0;
    o[9]  = R21 * gw2 - R22 * gw1;
    o[10] = R22 * gw0 - R20 * gw2;
    o[11] = R20 * gw1 - R21 * gw0;

    const float dpv0 = (pv1 * gw2 - pv2 * gw1) - MGc * R20;
    const float dpv1 = (pv2 * gw0 - pv0 * gw2) - MGc * R21;
    const float dpv2 = (pv0 * gw1 - pv1 * gw0) - MGc * R22 + v[18];

    const float dpw0 = (pw1 * gw2 - pw2 * gw1) + (pv1 * gv2 - pv2 * gv1) + v[19];
    const float dpw1 = (pw2 * gw0 - pw0 * gw2) + (pv2 * gv0 - pv0 * gv2) + v[20];
    const float dpw2 = (pw0 * gw1 - pw1 * gw0) + (pv0 * gv1 - pv1 * gv0) + v[21];

    o[12] = dpv0 * M1INVc;
    o[13] = dpv1 * M1INVc;
    o[14] = dpv2 * M1INVc;
    o[15] = dpw0 * JI0c;
    o[16] = dpw1 * JI0c;
    o[17] = dpw2 * JI2c;

    o[18] = 0.0f; o[19] = 0.0f; o[20] = 0.0f; o[21] = 0.0f;
}

__device__ __forceinline__ uint32_t smem_u32(const void* p) {
    uint32_t a;
    asm("{ .reg .u64 t; cvta.to.shared.u64 t, %1; cvt.u32.u64 %0, t; }"
        : "=r"(a) : "l"(p));
    return a;
}

__global__ __launch_bounds__(TPB)
void SE3HamNODEGT_kernel(const float* __restrict__ in, float* __restrict__ out,
                         int nrows) {
    __shared__ alignas(16) float s[TILE_F];
    __shared__ alignas(8) unsigned long long mbar[NWARP];

    const int tid  = threadIdx.x;
    const int wid  = tid >> 5;
    const int lane = tid & 31;

    const long long base_row  = (long long)blockIdx.x * TILE_ROWS;
    const long long base_elem = base_row * ROW_F;

    const bool full = (base_row + TILE_ROWS) <= (long long)nrows;

    if (full) {
        // Per-warp chunk: rows [wid*32, wid*32+32)
        float* sp = s + wid * WARP_F;
        const uint32_t sc = smem_u32(sp);
        const uint32_t mb = smem_u32(&mbar[wid]);
        const float* gsrc = in + base_elem + (long long)wid * WARP_F;
        float* gdst = out + base_elem + (long long)wid * WARP_F;

        if (lane == 0) {
            asm volatile("mbarrier.init.shared::cta.b64 [%0], 1;" :: "r"(mb) : "memory");
            asm volatile("fence.proxy.async.shared::cta;" ::: "memory");
            asm volatile("mbarrier.arrive.expect_tx.shared::cta.b64 _, [%0], %1;"
                         :: "r"(mb), "r"((uint32_t)WARP_BYTES) : "memory");
            asm volatile("cp.async.bulk.shared::cta.global.mbarrier::complete_tx::bytes "
                         "[%0], [%1], %2, [%3];"
                         :: "r"(sc), "l"(gsrc), "r"((uint32_t)WARP_BYTES), "r"(mb)
                         : "memory");
        }
        __syncwarp();   // don't poll mbar before lane0 initialized it

        // Wait for this warp's chunk (phase 0).
        {
            uint32_t done = 0;
            while (!done) {
                asm volatile(
                    "{ .reg .pred p; "
                    "mbarrier.try_wait.parity.shared::cta.b64 p, [%1], 0, 10000000; "
                    "selp.b32 %0, 1, 0, p; }"
                    : "=r"(done) : "r"(mb) : "memory");
            }
        }

        // One row per lane; conflict-free float2 access (row start 8B aligned;
        // word stride 22 -> LDS.64 16-lane phases hit distinct banks).
        float v[ROW_F], o[ROW_F];
        {
            const float2* r2 = reinterpret_cast<const float2*>(sp) + lane * ROW_F2;
            #pragma unroll
            for (int k = 0; k < ROW_F2; k++) {
                float2 x = r2[k];
                v[2 * k]     = x.x;
                v[2 * k + 1] = x.y;
            }
        }

        se3_row_compute(v, o);

        {
            float2* w2 = reinterpret_cast<float2*>(sp) + lane * ROW_F2;
            #pragma unroll
            for (int k = 0; k < ROW_F2; k++)
                w2[k] = make_float2(o[2 * k], o[2 * k + 1]);
        }
        __syncwarp();   // all lanes' smem writes happen-before lane0's fence

        if (lane == 0) {
            asm volatile("fence.proxy.async.shared::cta;" ::: "memory");
            asm volatile("cp.async.bulk.global.shared::cta.bulk_group [%0], [%1], %2;"
                         :: "l"(gdst), "r"(sc), "r"((uint32_t)WARP_BYTES) : "memory");
            asm volatile("cp.async.bulk.commit_group;" ::: "memory");
            asm volatile("cp.async.bulk.wait_group.read 0;" ::: "memory");
        }
        // lane0 keeps the warp alive until the store has read smem.
    } else {
        // Tail block (not hit for BS=2e6): guarded scalar path.
        const long long total = (long long)nrows * ROW_F;
        for (int i = tid; i < TILE_F; i += TPB) {
            long long g = base_elem + i;
            if (g < total) s[i] = in[g];
        }
        __syncthreads();

        const long long row = base_row + tid;
        float v[ROW_F], o[ROW_F];
        if (row < nrows) {
            #pragma unroll
            for (int j = 0; j < ROW_F; j++) v[j] = s[tid * ROW_F + j];
            se3_row_compute(v, o);
            #pragma unroll
            for (int j = 0; j < ROW_F; j++) s[tid * ROW_F + j] = o[j];
        }
        __syncthreads();

        for (int i = tid; i < TILE_F; i += TPB) {
            long long g = base_elem + i;
            if (g < total) out[g] = s[i];
        }
    }
}

extern "C" void kernel_launch(void* const* d_in, const int* in_sizes, int n_in,
                              void* d_out, int out_size) {
    const float* in = nullptr;
    for (int i = 0; i < n_in; i++) {
        if (in_sizes[i] == out_size) { in = (const float*)d_in[i]; break; }
    }
    if (!in) {
        int best = 0;
        for (int i = 1; i < n_in; i++) if (in_sizes[i] > in_sizes[best]) best = i;
        in = (const float*)d_in[best];
    }

    const int nrows = out_size / ROW_F;
    const int blocks = (nrows + TILE_ROWS - 1) / TILE_ROWS;
    SE3HamNODEGT_kernel<<<blocks, TPB>>>(in, (float*)d_out, nrows);
}